// round 2
// baseline (speedup 1.0000x reference)
#include <cuda_runtime.h>

#define NB 64
#define LQ 256
#define EE 64
#define HH 64

// Scratch (static __device__ — no allocations allowed)
__device__ float g_vt[NB * LQ * EE];    // vt[n][l][k] = values[k][l][n]   (4 MB)
__device__ float g_attn[NB * EE * EE];  // attn[n][a][b]                   (1 MB)
__device__ float g_M[NB * EE * EE];     // M[n][e][k] = (W @ A_n)[e][k]    (1 MB)

// ---------------------------------------------------------------------------
// K0: transpose values[k][l][n] -> vt[n][l][k], one block per l
// ---------------------------------------------------------------------------
__global__ void __launch_bounds__(256) k_transpose(const float* __restrict__ values) {
    __shared__ float tile[64][65];
    const int l = blockIdx.x;
    const int tid = threadIdx.x;
#pragma unroll
    for (int i = 0; i < 4; i++) {
        int f = i * 256 + tid;          // float4 index 0..1023
        int k = f >> 4;                 // 0..63
        int n4 = f & 15;                // 0..15
        float4 v = *(const float4*)(values + ((k * LQ + l) * EE) + n4 * 4);
        tile[k][n4 * 4 + 0] = v.x;
        tile[k][n4 * 4 + 1] = v.y;
        tile[k][n4 * 4 + 2] = v.z;
        tile[k][n4 * 4 + 3] = v.w;
    }
    __syncthreads();
#pragma unroll
    for (int i = 0; i < 4; i++) {
        int f = i * 256 + tid;
        int nn = f >> 4;
        int k4 = f & 15;
        float4 v = make_float4(tile[k4 * 4 + 0][nn], tile[k4 * 4 + 1][nn],
                               tile[k4 * 4 + 2][nn], tile[k4 * 4 + 3][nn]);
        *(float4*)(g_vt + ((nn * LQ + l) * EE) + k4 * 4) = v;
    }
}

// ---------------------------------------------------------------------------
// K1: energy[a][b] = sum_l query[n,l,a]*keys[n,l,b]; softmax rows -> g_attn
// grid: 128 blocks = (n, half of the 64 a-rows)
// ---------------------------------------------------------------------------
__global__ void __launch_bounds__(256) k_attn(const float* __restrict__ query,
                                              const float* __restrict__ keys) {
    const int n = blockIdx.x >> 1;
    const int half = blockIdx.x & 1;
    __shared__ float sQ[32][32];   // [l'][a_local]
    __shared__ float sK[32][64];   // [l'][b]
    __shared__ float sE[32][68];
    const int tid = threadIdx.x;
    const int a0 = (tid >> 4) * 2;  // 0..30 step 2
    const int b0 = (tid & 15) * 4;  // 0..60 step 4

    float a00 = 0.f, a01 = 0.f, a02 = 0.f, a03 = 0.f;
    float a10 = 0.f, a11 = 0.f, a12 = 0.f, a13 = 0.f;

    for (int l0 = 0; l0 < LQ; l0 += 32) {
        {
            int lp = tid >> 3;  // 0..31
            int q4 = tid & 7;   // 0..7
            float4 v = *(const float4*)(query + ((n * LQ + l0 + lp) * EE) + half * 32 + q4 * 4);
            *(float4*)&sQ[lp][q4 * 4] = v;
        }
#pragma unroll
        for (int j = 0; j < 2; j++) {
            int f = j * 256 + tid;
            int lp = f >> 4;
            int b4 = f & 15;
            float4 v = *(const float4*)(keys + ((n * LQ + l0 + lp) * EE) + b4 * 4);
            *(float4*)&sK[lp][b4 * 4] = v;
        }
        __syncthreads();
#pragma unroll
        for (int lp = 0; lp < 32; lp++) {
            float2 qv = *(const float2*)&sQ[lp][a0];
            float4 kv = *(const float4*)&sK[lp][b0];
            a00 += qv.x * kv.x; a01 += qv.x * kv.y; a02 += qv.x * kv.z; a03 += qv.x * kv.w;
            a10 += qv.y * kv.x; a11 += qv.y * kv.y; a12 += qv.y * kv.z; a13 += qv.y * kv.w;
        }
        __syncthreads();
    }
    *(float4*)&sE[a0][b0]     = make_float4(a00, a01, a02, a03);
    *(float4*)&sE[a0 + 1][b0] = make_float4(a10, a11, a12, a13);
    __syncthreads();

    // softmax: 8 warps x 4 rows each (32 rows in this half); hd=1 so no scale
    const int w = tid >> 5, lane = tid & 31;
#pragma unroll
    for (int r = 0; r < 4; r++) {
        int row = w * 4 + r;
        float v0 = sE[row][lane];
        float v1 = sE[row][lane + 32];
        float m = fmaxf(v0, v1);
#pragma unroll
        for (int off = 16; off; off >>= 1) m = fmaxf(m, __shfl_xor_sync(0xffffffffu, m, off));
        float e0 = __expf(v0 - m);
        float e1 = __expf(v1 - m);
        float s = e0 + e1;
#pragma unroll
        for (int off = 16; off; off >>= 1) s += __shfl_xor_sync(0xffffffffu, s, off);
        float inv = 1.0f / s;
        float* dst = g_attn + (n * EE + half * 32 + row) * EE;
        dst[lane] = e0 * inv;
        dst[lane + 32] = e1 * inv;
    }
}

// ---------------------------------------------------------------------------
// K2: M_n[e][k] = sum_e' W[e][e'] * attn[n][e'][k]   (fold fc into attn)
// grid: 64 blocks (one per n)
// ---------------------------------------------------------------------------
__global__ void __launch_bounds__(256) k_M(const float* __restrict__ W) {
    const int n = blockIdx.x;
    __shared__ float sWt[64][68];  // sWt[e'][e] = W[e][e']
    __shared__ float sA[64][68];   // sA[e'][k]
    const int tid = threadIdx.x;
#pragma unroll
    for (int i = 0; i < 16; i++) {
        int idx = i * 256 + tid;
        int r = idx >> 6, c = idx & 63;
        sWt[c][r] = W[idx];                       // transpose W on the fly
        sA[r][c] = g_attn[n * 4096 + idx];
    }
    __syncthreads();
    const int e0 = (tid >> 4) * 4;
    const int k0 = (tid & 15) * 4;
    float acc[4][4] = {};
#pragma unroll
    for (int ep = 0; ep < 64; ep++) {
        float4 wv = *(const float4*)&sWt[ep][e0];
        float4 av = *(const float4*)&sA[ep][k0];
        acc[0][0] += wv.x * av.x; acc[0][1] += wv.x * av.y; acc[0][2] += wv.x * av.z; acc[0][3] += wv.x * av.w;
        acc[1][0] += wv.y * av.x; acc[1][1] += wv.y * av.y; acc[1][2] += wv.y * av.z; acc[1][3] += wv.y * av.w;
        acc[2][0] += wv.z * av.x; acc[2][1] += wv.z * av.y; acc[2][2] += wv.z * av.z; acc[2][3] += wv.z * av.w;
        acc[3][0] += wv.w * av.x; acc[3][1] += wv.w * av.y; acc[3][2] += wv.w * av.z; acc[3][3] += wv.w * av.w;
    }
#pragma unroll
    for (int i = 0; i < 4; i++) {
        *(float4*)(g_M + ((n * 64 + e0 + i) * 64) + k0) =
            make_float4(acc[i][0], acc[i][1], acc[i][2], acc[i][3]);
    }
}

// ---------------------------------------------------------------------------
// K3: f[n,l,e] = b[e] + sum_k vt[n,l,k]*M_n[e,k]; LayerNorm over e;
//     broadcast the row to all 64 h slots of the output.
// grid: 512 blocks = (n, 32-l chunk); 256 thr = 64 e-lanes x 4 l-lanes
// ---------------------------------------------------------------------------
__global__ void __launch_bounds__(256) k_out(const float* __restrict__ bias,
                                             const float* __restrict__ lnw,
                                             const float* __restrict__ lnb,
                                             float* __restrict__ out) {
    const int n = blockIdx.x >> 3;
    const int lc = blockIdx.x & 7;
    const int tid = threadIdx.x;
    const int e = tid & 63;
    const int ls = tid >> 6;

    __shared__ float sv[4][64];
    __shared__ float red[8][2];
    __shared__ float sb[64], sw[64], sbeta[64];
    if (tid < 64) {
        sb[tid] = bias[tid];
        sw[tid] = lnw[tid];
        sbeta[tid] = lnb[tid];
    }

    // cache this thread's M row in registers (4 ls-lanes share each row; L1 hit)
    float Mreg[64];
    const float4* m4 = (const float4*)(g_M + (n * 64 + e) * 64);
#pragma unroll
    for (int j = 0; j < 16; j++) {
        float4 t = m4[j];
        Mreg[4 * j + 0] = t.x;
        Mreg[4 * j + 1] = t.y;
        Mreg[4 * j + 2] = t.z;
        Mreg[4 * j + 3] = t.w;
    }

    const int w = tid >> 5;

    for (int g = 0; g < 8; g++) {
        const int lbase = lc * 32 + g * 4;
        __syncthreads();  // protect sv/red from previous iteration readers
        sv[tid >> 6][tid & 63] = g_vt[(n * LQ + lbase + (tid >> 6)) * EE + (tid & 63)];
        __syncthreads();

        float acc = sb[e];
        const float4* v4 = (const float4*)sv[ls];
#pragma unroll
        for (int k4 = 0; k4 < 16; k4++) {
            float4 v = v4[k4];
            acc += v.x * Mreg[4 * k4 + 0];
            acc += v.y * Mreg[4 * k4 + 1];
            acc += v.z * Mreg[4 * k4 + 2];
            acc += v.w * Mreg[4 * k4 + 3];
        }

        // LayerNorm reduction over the 64 e-lanes (2 warps per ls group)
        float s = acc, s2 = acc * acc;
#pragma unroll
        for (int off = 16; off; off >>= 1) {
            s += __shfl_xor_sync(0xffffffffu, s, off);
            s2 += __shfl_xor_sync(0xffffffffu, s2, off);
        }
        if ((tid & 31) == 0) {
            red[w][0] = s;
            red[w][1] = s2;
        }
        __syncthreads();
        float S = red[w][0] + red[w ^ 1][0];
        float S2 = red[w][1] + red[w ^ 1][1];
        float mu = S * (1.0f / 64.0f);
        float var = S2 * (1.0f / 64.0f) - mu * mu;
        float rinv = rsqrtf(var + 1e-5f);
        float y = (acc - mu) * rinv * sw[e] + sbeta[e];

        // broadcast to all 64 h copies (residual+LN makes output h-independent)
        const int l = lbase + ls;
        float* p = out + (n * LQ + l) * EE + e;
#pragma unroll 8
        for (int h = 0; h < HH; h++) {
            *p = y;
            p += NB * LQ * EE;  // 1,048,576 floats
        }
    }
}

// ---------------------------------------------------------------------------
extern "C" void kernel_launch(void* const* d_in, const int* in_sizes, int n_in,
                              void* d_out, int out_size) {
    const float* values = (const float*)d_in[0];
    const float* keys   = (const float*)d_in[1];
    const float* query  = (const float*)d_in[2];
    const float* W      = (const float*)d_in[3];
    const float* b      = (const float*)d_in[4];
    const float* lnw    = (const float*)d_in[5];
    const float* lnb    = (const float*)d_in[6];
    float* out = (float*)d_out;

    k_transpose<<<256, 256>>>(values);
    k_attn<<<128, 256>>>(query, keys);
    k_M<<<64, 256>>>(W);
    k_out<<<512, 256>>>(b, lnw, lnb, out);
}